// round 3
// baseline (speedup 1.0000x reference)
#include <cuda_runtime.h>

#define NN   4096
#define HH   128
#define CAP  192   // max degree capacity; Binomial(4096,0.02) max ~= 120

// Scratch (device globals: allocation-free per harness rules)
__device__ float4 g_edge[NN * CAP];   // (j_bits, decay, wc, pad) per edge
__device__ int    g_deg[NN];
__device__ float  g_h[NN * HH];
__device__ float  g_m[NN * HH];

// ---------------------------------------------------------------------------
// Build per-row edge list from adj (2% dense) with loop-invariant weights.
// One warp per row; 4-way load batching for MLP=4 on the adj scan.
// Ordered ballot compaction (deterministic).
// ---------------------------------------------------------------------------
__global__ __launch_bounds__(256) void build_edges_kernel(
    const float* __restrict__ adj, const float* __restrict__ dist)
{
    int row  = blockIdx.x * 8 + (threadIdx.x >> 5);
    int lane = threadIdx.x & 31;
    if (row >= NN) return;
    const float* arow = adj  + (long)row * NN;
    const float* drow = dist + (long)row * NN;
    unsigned lt = (1u << lane) - 1u;
    int base = 0;
    for (int c0 = 0; c0 < NN; c0 += 128) {
        float a0 = arow[c0 + lane];
        float a1 = arow[c0 + 32 + lane];
        float a2 = arow[c0 + 64 + lane];
        float a3 = arow[c0 + 96 + lane];
        unsigned m0 = __ballot_sync(0xffffffffu, a0 != 0.0f);
        unsigned m1 = __ballot_sync(0xffffffffu, a1 != 0.0f);
        unsigned m2 = __ballot_sync(0xffffffffu, a2 != 0.0f);
        unsigned m3 = __ballot_sync(0xffffffffu, a3 != 0.0f);
#pragma unroll
        for (int q = 0; q < 4; q++) {
            float    a    = (q == 0) ? a0 : (q == 1) ? a1 : (q == 2) ? a2 : a3;
            unsigned mask = (q == 0) ? m0 : (q == 1) ? m1 : (q == 2) ? m2 : m3;
            int      col  = c0 + q * 32 + lane;
            if (a != 0.0f) {
                int pos = base + __popc(mask & lt);
                if (pos < CAP) {
                    float d     = drow[col];
                    float decay = __expf(d * (-1.0f / 3.0f));
                    float r     = fmaxf(d, 1e-6f);
                    float inv   = 3.5f / r;
                    float i2    = inv * inv;
                    float i6    = i2 * i2 * i2;
                    float wc    = 0.04f * (i6 * i6 - i6);
                    g_edge[row * CAP + pos] =
                        make_float4(__int_as_float(col), decay, wc, 0.0f);
                }
            }
            base += __popc(mask);
        }
    }
    if (lane == 0) g_deg[row] = (base < CAP) ? base : CAP;
}

// ---------------------------------------------------------------------------
// h = x @ W_in + b_in      (4096x64 @ 64x128); 8 rows/block, grid 512
// ---------------------------------------------------------------------------
__global__ __launch_bounds__(128) void in_proj_kernel(
    const float* __restrict__ x, const float* __restrict__ W,
    const float* __restrict__ b)
{
    __shared__ float sx[8 * 64];
    int c  = threadIdx.x;
    int r0 = blockIdx.x * 8;
    for (int i = threadIdx.x; i < 8 * 64; i += 128)
        sx[i] = x[(long)r0 * 64 + i];
    __syncthreads();

    float acc[8];
#pragma unroll
    for (int r = 0; r < 8; r++) acc[r] = 0.0f;

#pragma unroll 4
    for (int k = 0; k < 64; k += 4) {
        float w0 = W[(k + 0) * HH + c];
        float w1 = W[(k + 1) * HH + c];
        float w2 = W[(k + 2) * HH + c];
        float w3 = W[(k + 3) * HH + c];
#pragma unroll
        for (int r = 0; r < 8; r++) {
            float4 xv = *(const float4*)&sx[r * 64 + k];
            acc[r] = fmaf(xv.x, w0, fmaf(xv.y, w1, fmaf(xv.z, w2, fmaf(xv.w, w3, acc[r]))));
        }
    }
    float bias = b[c];
#pragma unroll
    for (int r = 0; r < 8; r++)
        g_h[(long)(r0 + r) * HH + c] = acc[r] + bias;
}

// ---------------------------------------------------------------------------
// m_i = sum_{j in N(i)} (decay_ij * relu(<h_i, h_j>) + wc_ij) * h_j
// One block (4 warps) per row. Each warp processes 4 edges at a time:
// 8-lane subgroup per edge, lane covers 16 hidden dims (4 x float4).
// Reduction = 3 shfl levels within the subgroup; 16+ LDGs in flight per warp.
// ---------------------------------------------------------------------------
__global__ __launch_bounds__(128) void msg_kernel()
{
    __shared__ float s_hi[HH];
    __shared__ float s_part[16][132];   // padded rows: stride 132 kills conflicts
    int row  = blockIdx.x;
    int tid  = threadIdx.x;
    int wid  = tid >> 5;
    int lane = tid & 31;
    int sub  = lane >> 3;    // 0..3 : which edge within the warp's group
    int sl   = lane & 7;     // 0..7 : 16-dim slice owner

    s_hi[tid] = g_h[(long)row * HH + tid];
    __syncthreads();

    // hi slice for this lane: dims [sl*16, sl*16+16)
    float4 hi0 = *(const float4*)&s_hi[sl * 16 + 0];
    float4 hi1 = *(const float4*)&s_hi[sl * 16 + 4];
    float4 hi2 = *(const float4*)&s_hi[sl * 16 + 8];
    float4 hi3 = *(const float4*)&s_hi[sl * 16 + 12];

    int deg = g_deg[row];
    const float4* ebase = &g_edge[row * CAP];

    float4 a0 = make_float4(0.f, 0.f, 0.f, 0.f);
    float4 a1 = a0, a2 = a0, a3 = a0;

    for (int e0 = wid * 4; e0 < deg; e0 += 16) {
        int  e     = e0 + sub;
        bool valid = (e < deg);
        float4 em = valid ? ebase[e] : make_float4(0.f, 0.f, 0.f, 0.f);
        int j = valid ? __float_as_int(em.x) : 0;
        const float* hjp = &g_h[(long)j * HH + sl * 16];
        float4 hj0 = *(const float4*)&hjp[0];
        float4 hj1 = *(const float4*)&hjp[4];
        float4 hj2 = *(const float4*)&hjp[8];
        float4 hj3 = *(const float4*)&hjp[12];

        float dot = hi0.x * hj0.x + hi0.y * hj0.y + hi0.z * hj0.z + hi0.w * hj0.w
                  + hi1.x * hj1.x + hi1.y * hj1.y + hi1.z * hj1.z + hi1.w * hj1.w
                  + hi2.x * hj2.x + hi2.y * hj2.y + hi2.z * hj2.z + hi2.w * hj2.w
                  + hi3.x * hj3.x + hi3.y * hj3.y + hi3.z * hj3.z + hi3.w * hj3.w;
        dot += __shfl_xor_sync(0xffffffffu, dot, 1);
        dot += __shfl_xor_sync(0xffffffffu, dot, 2);
        dot += __shfl_xor_sync(0xffffffffu, dot, 4);
        float coef = fmaf(em.y, fmaxf(dot, 0.0f), em.z);   // 0 when invalid

        a0.x = fmaf(coef, hj0.x, a0.x); a0.y = fmaf(coef, hj0.y, a0.y);
        a0.z = fmaf(coef, hj0.z, a0.z); a0.w = fmaf(coef, hj0.w, a0.w);
        a1.x = fmaf(coef, hj1.x, a1.x); a1.y = fmaf(coef, hj1.y, a1.y);
        a1.z = fmaf(coef, hj1.z, a1.z); a1.w = fmaf(coef, hj1.w, a1.w);
        a2.x = fmaf(coef, hj2.x, a2.x); a2.y = fmaf(coef, hj2.y, a2.y);
        a2.z = fmaf(coef, hj2.z, a2.z); a2.w = fmaf(coef, hj2.w, a2.w);
        a3.x = fmaf(coef, hj3.x, a3.x); a3.y = fmaf(coef, hj3.y, a3.y);
        a3.z = fmaf(coef, hj3.z, a3.z); a3.w = fmaf(coef, hj3.w, a3.w);
    }

    int cp = wid * 4 + sub;   // 16 partial copies
    *(float4*)&s_part[cp][sl * 16 + 0]  = a0;
    *(float4*)&s_part[cp][sl * 16 + 4]  = a1;
    *(float4*)&s_part[cp][sl * 16 + 8]  = a2;
    *(float4*)&s_part[cp][sl * 16 + 12] = a3;
    __syncthreads();

    float s = 0.0f;
#pragma unroll
    for (int k = 0; k < 16; k++) s += s_part[k][tid];
    g_m[(long)row * HH + tid] = s;
}

// ---------------------------------------------------------------------------
// Fused update: t = relu([h|m]@W1+b1); delta = t@W2+b2; out = LN(h+delta)
// 4 rows/block -> grid 1024 (27.7 warps/SM). Intermediates in smem.
// ---------------------------------------------------------------------------
__global__ __launch_bounds__(128) void update_kernel(
    const float* __restrict__ W1, const float* __restrict__ b1,
    const float* __restrict__ W2, const float* __restrict__ b2,
    const float* __restrict__ gamma, const float* __restrict__ beta,
    float* __restrict__ out)
{
    __shared__ float s_cat[4 * 256];   // [r][0:128)=h, [r][128:256)=m, later y
    __shared__ float s_t[4 * 128];
    int c  = threadIdx.x;
    int r0 = blockIdx.x * 4;

    for (int i = threadIdx.x; i < 4 * 128; i += 128) {
        int r = i >> 7, k = i & 127;
        s_cat[r * 256 + k]       = g_h[(long)(r0 + r) * HH + k];
        s_cat[r * 256 + 128 + k] = g_m[(long)(r0 + r) * HH + k];
    }
    __syncthreads();

    // ---- mlp1: t = relu(cat @ W1 + b1) ----
    float acc[4];
#pragma unroll
    for (int r = 0; r < 4; r++) acc[r] = 0.0f;
#pragma unroll 8
    for (int k = 0; k < 256; k += 4) {
        float w0 = W1[(k + 0) * HH + c];
        float w1 = W1[(k + 1) * HH + c];
        float w2 = W1[(k + 2) * HH + c];
        float w3 = W1[(k + 3) * HH + c];
#pragma unroll
        for (int r = 0; r < 4; r++) {
            float4 cv = *(const float4*)&s_cat[r * 256 + k];
            acc[r] = fmaf(cv.x, w0, fmaf(cv.y, w1, fmaf(cv.z, w2, fmaf(cv.w, w3, acc[r]))));
        }
    }
    {
        float bias = b1[c];
#pragma unroll
        for (int r = 0; r < 4; r++)
            s_t[r * 128 + c] = fmaxf(acc[r] + bias, 0.0f);
    }
    __syncthreads();

    // ---- mlp2: delta = t @ W2 + b2 ----
#pragma unroll
    for (int r = 0; r < 4; r++) acc[r] = 0.0f;
#pragma unroll 8
    for (int k = 0; k < 128; k += 4) {
        float w0 = W2[(k + 0) * HH + c];
        float w1 = W2[(k + 1) * HH + c];
        float w2 = W2[(k + 2) * HH + c];
        float w3 = W2[(k + 3) * HH + c];
#pragma unroll
        for (int r = 0; r < 4; r++) {
            float4 tv = *(const float4*)&s_t[r * 128 + k];
            acc[r] = fmaf(tv.x, w0, fmaf(tv.y, w1, fmaf(tv.z, w2, fmaf(tv.w, w3, acc[r]))));
        }
    }
    // y = h + delta + b2 -> overwrite m-region (all m reads finished pre-sync)
    {
        float bias = b2[c];
#pragma unroll
        for (int r = 0; r < 4; r++)
            s_cat[r * 256 + 128 + c] = s_cat[r * 256 + c] + acc[r] + bias;
    }
    __syncthreads();

    // ---- layernorm: warp wid handles row wid; lane owns 4 cols ----
    int wid  = c >> 5;
    int lane = c & 31;
    float4 gm = *(const float4*)&gamma[lane * 4];
    float4 bt = *(const float4*)&beta[lane * 4];
    {
        int r = wid;
        float4 yv = *(const float4*)&s_cat[r * 256 + 128 + lane * 4];
        float s = yv.x + yv.y + yv.z + yv.w;
#pragma unroll
        for (int o = 16; o > 0; o >>= 1)
            s += __shfl_xor_sync(0xffffffffu, s, o);
        float mu = s * (1.0f / 128.0f);
        float dx = yv.x - mu, dy = yv.y - mu, dz = yv.z - mu, dw = yv.w - mu;
        float sq = dx * dx + dy * dy + dz * dz + dw * dw;
#pragma unroll
        for (int o = 16; o > 0; o >>= 1)
            sq += __shfl_xor_sync(0xffffffffu, sq, o);
        float rs = rsqrtf(sq * (1.0f / 128.0f) + 1e-5f);
        float4 o4;
        o4.x = dx * rs * gm.x + bt.x;
        o4.y = dy * rs * gm.y + bt.y;
        o4.z = dz * rs * gm.z + bt.z;
        o4.w = dw * rs * gm.w + bt.w;
        *(float4*)&out[(long)(r0 + r) * HH + lane * 4] = o4;
    }
}

// ---------------------------------------------------------------------------
extern "C" void kernel_launch(void* const* d_in, const int* in_sizes, int n_in,
                              void* d_out, int out_size)
{
    const float* x     = (const float*)d_in[0];
    const float* adj   = (const float*)d_in[1];
    const float* dist  = (const float*)d_in[2];
    const float* W_in  = (const float*)d_in[3];
    const float* b_in  = (const float*)d_in[4];
    // d_in[5] = W_msg, d_in[6] = b_msg : dead code in the reference
    const float* W_u1  = (const float*)d_in[7];
    const float* b_u1  = (const float*)d_in[8];
    const float* W_u2  = (const float*)d_in[9];
    const float* b_u2  = (const float*)d_in[10];
    const float* gamma = (const float*)d_in[11];
    const float* beta  = (const float*)d_in[12];
    float* out = (float*)d_out;

    float* h_ptr = nullptr;
    cudaGetSymbolAddress((void**)&h_ptr, g_h);

    build_edges_kernel<<<NN / 8, 256>>>(adj, dist);
    in_proj_kernel<<<NN / 8, 128>>>(x, W_in, b_in);
    for (int s = 0; s < 3; s++) {
        msg_kernel<<<NN, 128>>>();
        update_kernel<<<NN / 4, 128>>>(W_u1, b_u1, W_u2, b_u2, gamma, beta,
                                       (s == 2) ? out : h_ptr);
    }
}